// round 12
// baseline (speedup 1.0000x reference)
#include <cuda_runtime.h>
#include <cstdint>

#define H 256
#define DD 64
#define NPAIR 128           // n-pairs
#define NBM (2 * NPAIR)     // k_main blocks: (pair, t-half)

// ---------------- persistent device state (no allocations) ----------------
__device__ float g_G[H * H];                      // Gram: G[m,t]
__device__ float g_h1[H], g_h2[H], g_h3[H], g_h4[H], g_s[H];
__device__ float g_gd[4][H];                      // g'..g'''' at a_n
__device__ float g_part[NPAIR][12];               // hf=1 partial contractions
__device__ unsigned int g_flag[NPAIR];            // pair exchange flags (init 0)
__device__ double g_accum = 0.0;
__device__ unsigned int g_done = 0;

// ---------------- kernel 1: Gram (blocks 0-127) + chain/g-chain (block 128) ----
__global__ __launch_bounds__(256) void k_pre(
    const float* __restrict__ x,  const float* __restrict__ W1,
    const float* __restrict__ b1, const float* __restrict__ W2,
    const float* __restrict__ b2)
{
    int tid = threadIdx.x;
    if (blockIdx.x < 128) {
        __shared__ float srow[2][DD];
        int m0 = 2 * blockIdx.x;
        if (tid < 2 * DD) srow[tid >> 6][tid & 63] = W1[(m0 + (tid >> 6)) * DD + (tid & 63)];
        __syncthreads();
        const float4* myr = (const float4*)(W1 + tid * DD);
        float a0 = 0.f, a1 = 0.f;
#pragma unroll
        for (int i = 0; i < DD / 4; i++) {
            float4 v = __ldg(myr + i);
            a0 += srow[0][4*i]*v.x + srow[0][4*i+1]*v.y + srow[0][4*i+2]*v.z + srow[0][4*i+3]*v.w;
            a1 += srow[1][4*i]*v.x + srow[1][4*i+1]*v.y + srow[1][4*i+2]*v.z + srow[1][4*i+3]*v.w;
        }
        g_G[(m0 + 0) * H + tid] = a0;
        g_G[(m0 + 1) * H + tid] = a1;
    } else {
        // layer-1 chain vectors + layer-2 g-chain
        __shared__ float sx[DD];
        __shared__ float sh[H];
        if (tid < DD) sx[tid] = x[tid];
        __syncthreads();

        float z = b1[tid], s = 0.f;
        const float4* wr = (const float4*)(W1 + tid * DD);
#pragma unroll
        for (int i = 0; i < DD / 4; i++) {
            float4 w = __ldg(wr + i);
            float4 xv = *(const float4*)(sx + 4 * i);
            z += w.x * xv.x + w.y * xv.y + w.z * xv.z + w.w * xv.w;
            s += w.x * w.x + w.y * w.y + w.z * w.z + w.w * w.w;
        }
        float h = tanhf(z), w = 1.f - h * h;
        g_h1[tid] = w;
        g_h2[tid] = -2.f * h * w;
        g_h3[tid] = (4.f * h * h - 2.f * w) * w;
        g_h4[tid] = (16.f * w - 8.f * h * h) * h * w;
        g_s[tid] = s;
        sh[tid] = h;
        __syncthreads();

        float a = b2[tid];
        const float4* w2r = (const float4*)(W2 + tid * H);
#pragma unroll 8
        for (int i = 0; i < H / 4; i++) {
            float4 wv = __ldg(w2r + i);
            a += wv.x * sh[4*i] + wv.y * sh[4*i+1] + wv.z * sh[4*i+2] + wv.w * sh[4*i+3];
        }
        float g = tanhf(a), gw = 1.f - g * g;
        g_gd[0][tid] = gw;
        g_gd[1][tid] = -2.f * g * gw;
        g_gd[2][tid] = (4.f * g * g - 2.f * gw) * gw;
        g_gd[3][tid] = (16.f * gw - 8.f * g * g) * g * gw;
    }
}

// ---------------- kernel 2: contraction blocks (pair p, t-half hf) ----------------
// M[n,t] = sum_m A[n,m] G[m,t]; P[n,t] = sum_m B[n,m] G[m,t]^2  (full m-sum,
// t restricted to this block's half). Block reduces to 12 scalars
// {Q,R,Z,U,L,Y} x 2n (L,Y over this block's m-half). hf=1 publishes; hf=0
// combines, applies val formula, accumulates; last hf=0 block writes out.
__global__ __launch_bounds__(256, 2) void k_main(
    const float* __restrict__ W2, const float* __restrict__ W3,
    float* __restrict__ out)
{
    __shared__ float  sP[8 * 32 * 16];   // partials [ms][ts][16] = 16KB
    __shared__ float4 sAB[H];            // {A0, A1, B0, B1} per m/t (4KB)
    __shared__ float  sU0[H], sU1[H];
    __shared__ float  sred[4][12];

    int tid = threadIdx.x;
    int bx = blockIdx.x;
    int p = bx >> 1, hf = bx & 1;
    int wid = tid >> 5, lane = tid & 31;
    int n0 = 2 * p;

    // ---- setup: coefficient vectors (full m range) ----
    {
        int m = tid;
        float h1 = g_h1[m], h2 = g_h2[m], h3 = g_h3[m], s = g_s[m];
        float w20 = __ldg(&W2[n0 * H + m]);
        float w21 = __ldg(&W2[(n0 + 1) * H + m]);
        sAB[m] = make_float4(w20 * h1, w21 * h1, w20 * h2, w21 * h2);
        sU0[m] = w20 * h3 * s;
        sU1[m] = w21 * h3 * s;
    }
    __syncthreads();

    // per-thread L/Y partials over this block's m-half (threads 0-127)
    float pL0 = 0.f, pL1 = 0.f, pY0 = 0.f, pY1 = 0.f;
    if (tid < 128) {
        int mm = hf * 128 + tid;
        float s = g_s[mm], h4 = g_h4[mm];
        float w20 = __ldg(&W2[n0 * H + mm]);
        float w21 = __ldg(&W2[(n0 + 1) * H + mm]);
        float4 ab = sAB[mm];
        pL0 = ab.z * s;  pL1 = ab.w * s;
        pY0 = w20 * h4 * s * s;
        pY1 = w21 * h4 * s * s;
    }

    // ---- phase 1: pipelined G stream; thread = (ms = tid>>5, ts = tid&31) ----
    // t-cols: 4*(hf*32 + ts) .. +3 ; m-rows: 32*ms .. +31
    int ms = tid >> 5, ts = tid & 31;
    float M0[4] = {0,0,0,0}, M1[4] = {0,0,0,0};
    float P0[4] = {0,0,0,0}, P1[4] = {0,0,0,0};

    const float4* Gp = (const float4*)g_G + (32 * ms) * (H / 4) + hf * 32 + ts;
    const float4* abp = sAB + 32 * ms;

    float4 buf[2][8];
#pragma unroll
    for (int u = 0; u < 8; u++) buf[0][u] = __ldg(Gp + u * (H / 4));

#pragma unroll
    for (int bb = 0; bb < 4; bb++) {
        int cur = bb & 1, nxt = cur ^ 1;
        if (bb < 3) {
#pragma unroll
            for (int u = 0; u < 8; u++)
                buf[nxt][u] = __ldg(Gp + (8 * (bb + 1) + u) * (H / 4));
        }
#pragma unroll
        for (int u = 0; u < 8; u++) {
            float4 ab = abp[8 * bb + u];
            float4 g = buf[cur][u];
            M0[0] += ab.x * g.x;  M0[1] += ab.x * g.y;  M0[2] += ab.x * g.z;  M0[3] += ab.x * g.w;
            M1[0] += ab.y * g.x;  M1[1] += ab.y * g.y;  M1[2] += ab.y * g.z;  M1[3] += ab.y * g.w;
            float gg0 = g.x * g.x, gg1 = g.y * g.y, gg2 = g.z * g.z, gg3 = g.w * g.w;
            P0[0] += ab.z * gg0;  P0[1] += ab.z * gg1;  P0[2] += ab.z * gg2;  P0[3] += ab.z * gg3;
            P1[0] += ab.w * gg0;  P1[1] += ab.w * gg1;  P1[2] += ab.w * gg2;  P1[3] += ab.w * gg3;
        }
    }
    {
        float4* sp = (float4*)(sP + (ms * 32 + ts) * 16);
        sp[0] = make_float4(M0[0], M0[1], M0[2], M0[3]);
        sp[1] = make_float4(M1[0], M1[1], M1[2], M1[3]);
        sp[2] = make_float4(P0[0], P0[1], P0[2], P0[3]);
        sp[3] = make_float4(P1[0], P1[1], P1[2], P1[3]);
    }
    __syncthreads();

    // ---- phase 2: combine ms partials + contraction (threads 0-127) ----
    float pv[12];
    if (tid < 128) {
        int tts = tid >> 2, c = tid & 3;
        float m0 = 0.f, m1 = 0.f, q0 = 0.f, q1 = 0.f;
#pragma unroll
        for (int w = 0; w < 8; w++) {
            const float* sp = sP + (w * 32 + tts) * 16;
            m0 += sp[c];
            m1 += sp[4 + c];
            q0 += sp[8 + c];
            q1 += sp[12 + c];
        }
        int gt = hf * 128 + tid;     // global t for coefficient lookup
        float4 ab = sAB[gt];
        pv[0]  = ab.x * m0;       pv[1]  = ab.z * m0 * m0;  pv[2]  = ab.z * q0;
        pv[3]  = sU0[gt] * m0;    pv[4]  = pL0;             pv[5]  = pY0;
        pv[6]  = ab.y * m1;       pv[7]  = ab.w * m1 * m1;  pv[8]  = ab.w * q1;
        pv[9]  = sU1[gt] * m1;    pv[10] = pL1;             pv[11] = pY1;

#pragma unroll
        for (int k = 0; k < 12; k++) {
            float v = pv[k];
#pragma unroll
            for (int s2 = 16; s2 > 0; s2 >>= 1) v += __shfl_down_sync(0xFFFFFFFFu, v, s2);
            pv[k] = v;
        }
        if (lane == 0) {
#pragma unroll
            for (int k = 0; k < 12; k++) sred[wid][k] = pv[k];
        }
    }
    __syncthreads();

    if (tid == 0) {
        float sc[12];
#pragma unroll
        for (int k = 0; k < 12; k++)
            sc[k] = sred[0][k] + sred[1][k] + sred[2][k] + sred[3][k];

        if (hf == 1) {
#pragma unroll
            for (int k = 0; k < 12; k++) g_part[p][k] = sc[k];
            __threadfence();
            atomicExch(&g_flag[p], 1u);
        } else {
            while (atomicAdd(&g_flag[p], 0u) == 0u) { __nanosleep(32); }
            __threadfence();
            double dsum = 0.0;
#pragma unroll
            for (int nn = 0; nn < 2; nn++) {
                float Q = sc[nn*6+0] + g_part[p][nn*6+0];
                float R = sc[nn*6+1] + g_part[p][nn*6+1];
                float Z = sc[nn*6+2] + g_part[p][nn*6+2];
                float U = sc[nn*6+3] + g_part[p][nn*6+3];
                float L = sc[nn*6+4] + g_part[p][nn*6+4];
                float Y = sc[nn*6+5] + g_part[p][nn*6+5];
                int n = n0 + nn;
                float g1 = g_gd[0][n], g2 = g_gd[1][n], g3 = g_gd[2][n], g4 = g_gd[3][n];
                float val = g4 * Q * Q
                          + g3 * (2.f * L * Q + 4.f * R)
                          + g2 * (L * L + 2.f * Z + 4.f * U)
                          + g1 * Y;
                dsum += (double)(__ldg(&W3[n]) * val);
            }
            g_flag[p] = 0u;              // reset for next replay
            atomicAdd(&g_accum, dsum);
            __threadfence();
            unsigned int old = atomicAdd(&g_done, 1u);
            if (old == NPAIR - 1) {
                double r = atomicAdd(&g_accum, 0.0);
                out[0] = (float)r;
                g_accum = 0.0;
                g_done = 0u;
                __threadfence();
            }
        }
    }
}

// ---------------- launch ----------------
extern "C" void kernel_launch(void* const* d_in, const int* in_sizes, int n_in,
                              void* d_out, int out_size) {
    const float* x  = (const float*)d_in[0];
    const float* W1 = (const float*)d_in[1];
    const float* b1 = (const float*)d_in[2];
    const float* W2 = (const float*)d_in[3];
    const float* b2 = (const float*)d_in[4];
    const float* W3 = (const float*)d_in[5];
    // d_in[6] = b3: does not affect the 4th derivative
    float* out = (float*)d_out;

    k_pre<<<129, 256>>>(x, W1, b1, W2, b2);
    k_main<<<NBM, 256>>>(W2, W3, out);
}